// round 9
// baseline (speedup 1.0000x reference)
#include <cuda_runtime.h>

// SerialResnet as a tabulated 1-D function, split table resident in SMEM.
//
// Build F on 2^15+1 grid points over [-6.5,6.5] (exact f32 chain). Eval is a
// persistent CTA/SM kernel: center region [-3.25,3.25) staged as {F,dF}
// float2 pairs (one LDS.64 per element), gaussian tails as scalar tables
// (2 LDS.32, ~0.1% of elements). Same grid step everywhere -> accuracy
// identical to the 2^15 single-table kernel. Build is overlapped with eval's
// x-prefetch via programmatic dependent launch.
//
// Raw-grid layout (dx = 13/32768):
//   left tail  : raw[0 .. NT]          covers x in [-6.5, -3.25]
//   center     : raw[NT .. NT+NC]      covers x in [-3.25, 3.25]   (NT=8192)
//   right tail : raw[3*NT .. 4*NT]     covers x in [3.25, 6.5]     (NC=16384)

#define NL 20
#define LOG2_NINT 15
#define N_INT (1 << LOG2_NINT)          // 32768 intervals over [-6.5, 6.5]
#define XLO (-6.5f)
#define XRANGE 13.0f

#define NT (N_INT / 4)                  // 8192 tail intervals each side
#define NC (N_INT / 2)                  // 16384 center intervals
#define SCALE ((float)N_INT / XRANGE)   // 1/dx

#define EVAL_THREADS 1024
// smem layout: pairs [0, 131072) | left [131072, +32784) | right
#define OFF_PAIR 0
#define OFF_LEFT (NC * 8)                                      // 131072
#define OFF_RIGHT (OFF_LEFT + (((NT + 1) * 4 + 15) / 16) * 16) // aligned
#define SMEM_BYTES (OFF_RIGHT + (NT + 1) * 4 + 16)

__device__ float g_rawtab[N_INT + 1];   // F at grid points

__device__ __forceinline__ float tanh_f32(float v) {
    float y;
    asm("tanh.approx.f32 %0, %1;" : "=f"(y) : "f"(v));
    return y;
}

// ---------------------------------------------------------------- build ----
__global__ __launch_bounds__(256)
void build_table_kernel(const float* __restrict__ W, const float* __restrict__ b) {
    // Allow the dependent eval kernel to launch and run its prologue.
    asm volatile("griddepcontrol.launch_dependents;");

    const int i = blockIdx.x * blockDim.x + threadIdx.x;
    if (i > N_INT) return;

    const float xi = XLO + (float)i * (XRANGE / (float)N_INT);
    float h0 = xi, h1 = xi;

#pragma unroll
    for (int l = 0; l < NL; ++l) {
        const float4 wl = __ldg(reinterpret_cast<const float4*>(W) + l);
        const float2 bl = __ldg(reinterpret_cast<const float2*>(b) + l);
        const float z0 = fmaf(wl.x, h0, fmaf(wl.y, h1, bl.x));
        const float z1 = fmaf(wl.z, h0, fmaf(wl.w, h1, bl.y));
        h0 += tanh_f32(z0);
        h1 += tanh_f32(z1);
    }
    g_rawtab[i] = 0.5f * (h0 + h1);
}

// ----------------------------------------------------------------- eval ----
__device__ __forceinline__ float interp1(const float2* __restrict__ s_pair,
                                         const float* __restrict__ s_left,
                                         const float* __restrict__ s_right,
                                         float xv) {
    // Center: idx in [0, NC) iff x in [-3.25, 3.25).  pair i == raw NT+i.
    const float idxf = fmaf(xv, SCALE, 3.25f * SCALE);
    const int i = __float2int_rd(idxf);
    if ((unsigned)i < (unsigned)NC) {
        const float frac = idxf - (float)i;
        const float2 p = s_pair[i];          // {F_i, dF_i} : one LDS.64
        return fmaf(frac, p.y, p.x);
    }
    // Tail (rare): scalar tables, clamped index extrapolates at range edges.
    const bool left = xv < 0.0f;
    const float tf = left ? fmaf(xv, SCALE, 6.5f * SCALE)
                          : fmaf(xv, SCALE, -3.25f * SCALE);
    int ti = __float2int_rd(tf);
    ti = max(0, min(ti, NT - 1));
    const float frac = tf - (float)ti;
    const float* tb = left ? s_left : s_right;
    const float f0 = tb[ti];
    const float f1 = tb[ti + 1];
    return fmaf(frac, f1 - f0, f0);
}

__global__ __launch_bounds__(EVAL_THREADS, 1)
void eval_kernel(const float* __restrict__ x, float* __restrict__ out, int n) {
    extern __shared__ float s_raw[];
    float2* __restrict__ s_pair = reinterpret_cast<float2*>((char*)s_raw + OFF_PAIR);
    float* __restrict__ s_left  = reinterpret_cast<float*>((char*)s_raw + OFF_LEFT);
    float* __restrict__ s_right = reinterpret_cast<float*>((char*)s_raw + OFF_RIGHT);

    const int tid = threadIdx.x;
    const float4* __restrict__ x4 = reinterpret_cast<const float4*>(x);
    float4* __restrict__ o4 = reinterpret_cast<float4*>(out);

    const int ngroups = n >> 2;
    const int stride = gridDim.x * EVAL_THREADS * 2;

    int g0 = blockIdx.x * EVAL_THREADS * 2 + tid;
    int g1 = g0 + EVAL_THREADS;

    // Prologue x loads: independent of the table -> issue before the PDL wait.
    float4 cur0, cur1;
    bool v0 = g0 < ngroups, v1 = g1 < ngroups;
    if (v0) cur0 = x4[g0];
    if (v1) cur1 = x4[g1];

    // Wait for build_table_kernel to complete (writes visible after this).
    asm volatile("griddepcontrol.wait;" ::: "memory");

    // Stage tables into smem.
    {
        const float* raw = g_rawtab;
        // Center pairs {F, dF}: raw indices [NT, NT+NC].
#pragma unroll
        for (int j = 0; j < NC / 4 / EVAL_THREADS; ++j) {
            const int k = j * EVAL_THREADS + tid;        // quad-pair group
            const int base = NT + 4 * k;
            const float4 a = *reinterpret_cast<const float4*>(raw + base);
            const float nx = raw[base + 4];
            float4 p01 = make_float4(a.x, a.y - a.x, a.y, a.z - a.y);
            float4 p23 = make_float4(a.z, a.w - a.z, a.w, nx - a.w);
            reinterpret_cast<float4*>(s_pair)[2 * k]     = p01;
            reinterpret_cast<float4*>(s_pair)[2 * k + 1] = p23;
        }
        // Left tail: raw [0, NT]; right tail: raw [3*NT, 4*NT].
#pragma unroll
        for (int j = 0; j < NT / 4 / EVAL_THREADS; ++j) {
            const int k = j * EVAL_THREADS + tid;
            reinterpret_cast<float4*>(s_left)[k] =
                reinterpret_cast<const float4*>(raw)[k];
            reinterpret_cast<float4*>(s_right)[k] =
                reinterpret_cast<const float4*>(raw + 3 * NT)[k];
        }
        if (tid == 0) s_left[NT] = raw[NT];
        if (tid == 1) s_right[NT] = raw[N_INT];
    }
    __syncthreads();

    while (v0) {
        const int n0 = g0 + stride, n1 = g1 + stride;
        const bool nv0 = n0 < ngroups, nv1 = n1 < ngroups;
        float4 nxt0, nxt1;
        if (nv0) nxt0 = x4[n0];
        if (nv1) nxt1 = x4[n1];

        float4 r0, r1;
        r0.x = interp1(s_pair, s_left, s_right, cur0.x);
        r0.y = interp1(s_pair, s_left, s_right, cur0.y);
        r0.z = interp1(s_pair, s_left, s_right, cur0.z);
        r0.w = interp1(s_pair, s_left, s_right, cur0.w);
        o4[g0] = r0;
        if (v1) {
            r1.x = interp1(s_pair, s_left, s_right, cur1.x);
            r1.y = interp1(s_pair, s_left, s_right, cur1.y);
            r1.z = interp1(s_pair, s_left, s_right, cur1.z);
            r1.w = interp1(s_pair, s_left, s_right, cur1.w);
            o4[g1] = r1;
        }

        cur0 = nxt0; cur1 = nxt1;
        g0 = n0; g1 = n1;
        v0 = nv0; v1 = nv1;
    }

    // Tail (n % 4 != 0): block 0.
    if (blockIdx.x == 0) {
        for (int i1 = (n & ~3) + tid; i1 < n; i1 += EVAL_THREADS) {
            out[i1] = interp1(s_pair, s_left, s_right, x[i1]);
        }
    }
}

extern "C" void kernel_launch(void* const* d_in, const int* in_sizes, int n_in,
                              void* d_out, int out_size) {
    const float* x = (const float*)d_in[0];
    const float* W = (const float*)d_in[1];
    const float* b = (const float*)d_in[2];
    float* out = (float*)d_out;

    const int n = in_sizes[0];

    static int n_sm = 0;
    static bool attr_set = false;
    if (!attr_set) {
        cudaDeviceGetAttribute(&n_sm, cudaDevAttrMultiProcessorCount, 0);
        if (n_sm <= 0) n_sm = 148;
        cudaFuncSetAttribute(eval_kernel,
                             cudaFuncAttributeMaxDynamicSharedMemorySize,
                             SMEM_BYTES);
        attr_set = true;
    }

    build_table_kernel<<<(N_INT + 1 + 255) / 256, 256>>>(W, b);

    cudaLaunchConfig_t cfg = {};
    cfg.gridDim = dim3(n_sm, 1, 1);
    cfg.blockDim = dim3(EVAL_THREADS, 1, 1);
    cfg.dynamicSmemBytes = SMEM_BYTES;
    cfg.stream = 0;
    cudaLaunchAttribute at[1];
    at[0].id = cudaLaunchAttributeProgrammaticStreamSerialization;
    at[0].val.programmaticStreamSerializationAllowed = 1;
    cfg.attrs = at;
    cfg.numAttrs = 1;
    cudaLaunchKernelEx(&cfg, eval_kernel, x, out, n);
}

// round 10
// speedup vs baseline: 1.0135x; 1.0135x over previous
#include <cuda_runtime.h>

// SerialResnet as a tabulated 1-D function; center table in SMEM, tails in L2.
//
// Build F on 2^15+1 grid points over [-6.5,6.5] (exact f32 chain). Eval:
// center region [-3.25,3.25) staged as a scalar f32 table (64 KB -> 2 CTAs
// per SM, 64 warps, full occupancy); gaussian tails (0.115% of x) interpolate
// straight from g_rawtab in L2 via __ldg. Same grid step everywhere ->
// accuracy identical to the 2^15 single-table kernel (rel_err ~4.3e-4).

#define NL 20
#define LOG2_NINT 15
#define N_INT (1 << LOG2_NINT)          // 32768 intervals over [-6.5, 6.5]
#define XLO (-6.5f)
#define XRANGE 13.0f

#define NT (N_INT / 4)                  // 8192: center starts at raw[NT]
#define NC (N_INT / 2)                  // 16384 center intervals
#define SCALE ((float)N_INT / XRANGE)   // 1/dx

#define EVAL_THREADS 1024
#define SMEM_BYTES ((NC + 1) * 4 + 16)  // 65556 B -> 2 CTAs/SM

__device__ float g_rawtab[N_INT + 1];   // F at grid points (L2-resident)

__device__ __forceinline__ float tanh_f32(float v) {
    float y;
    asm("tanh.approx.f32 %0, %1;" : "=f"(y) : "f"(v));
    return y;
}

// ---------------------------------------------------------------- build ----
__global__ __launch_bounds__(256)
void build_table_kernel(const float* __restrict__ W, const float* __restrict__ b) {
    asm volatile("griddepcontrol.launch_dependents;");

    const int i = blockIdx.x * blockDim.x + threadIdx.x;
    if (i > N_INT) return;

    const float xi = XLO + (float)i * (XRANGE / (float)N_INT);
    float h0 = xi, h1 = xi;

#pragma unroll
    for (int l = 0; l < NL; ++l) {
        const float4 wl = __ldg(reinterpret_cast<const float4*>(W) + l);
        const float2 bl = __ldg(reinterpret_cast<const float2*>(b) + l);
        const float z0 = fmaf(wl.x, h0, fmaf(wl.y, h1, bl.x));
        const float z1 = fmaf(wl.z, h0, fmaf(wl.w, h1, bl.y));
        h0 += tanh_f32(z0);
        h1 += tanh_f32(z1);
    }
    g_rawtab[i] = 0.5f * (h0 + h1);
}

// ----------------------------------------------------------------- eval ----
__device__ __forceinline__ float interp1(const float* __restrict__ s_tab, float xv) {
    // Center: i in [0, NC) iff x in [-3.25, 3.25). s_tab[i] == raw[NT+i].
    const float idxf = fmaf(xv, SCALE, 3.25f * SCALE);
    const int i = __float2int_rd(idxf);
    if ((unsigned)i < (unsigned)NC) {
        const float frac = idxf - (float)i;
        const float f0 = s_tab[i];
        const float f1 = s_tab[i + 1];
        return fmaf(frac, f1 - f0, f0);
    }
    // Tail (~0.115% of elements): interpolate from L2-resident raw table.
    const float gf = fmaf(xv, SCALE, 6.5f * SCALE);
    int gi = __float2int_rd(gf);
    gi = max(0, min(gi, N_INT - 1));
    const float frac = gf - (float)gi;
    const float f0 = __ldg(&g_rawtab[gi]);
    const float f1 = __ldg(&g_rawtab[gi + 1]);
    return fmaf(frac, f1 - f0, f0);
}

__global__ __launch_bounds__(EVAL_THREADS, 2)
void eval_kernel(const float* __restrict__ x, float* __restrict__ out, int n) {
    extern __shared__ float s_tab[];

    const int tid = threadIdx.x;

    asm volatile("griddepcontrol.wait;" ::: "memory");

    // Stage center table: raw[NT .. NT+NC] -> s_tab[0 .. NC].
    {
        const float4* src = reinterpret_cast<const float4*>(g_rawtab + NT);
        float4* dst = reinterpret_cast<float4*>(s_tab);
#pragma unroll
        for (int j = 0; j < (NC / 4) / EVAL_THREADS; ++j) {
            const int k = j * EVAL_THREADS + tid;
            dst[k] = src[k];
        }
        if (tid == 0) s_tab[NC] = g_rawtab[NT + NC];
    }
    __syncthreads();

    const float4* __restrict__ x4 = reinterpret_cast<const float4*>(x);
    float4* __restrict__ o4 = reinterpret_cast<float4*>(out);

    const int ngroups = n >> 2;
    const int stride = gridDim.x * EVAL_THREADS;

    for (int g = blockIdx.x * EVAL_THREADS + tid; g < ngroups; g += stride) {
        const float4 xv = x4[g];
        float4 ov;
        ov.x = interp1(s_tab, xv.x);
        ov.y = interp1(s_tab, xv.y);
        ov.z = interp1(s_tab, xv.z);
        ov.w = interp1(s_tab, xv.w);
        o4[g] = ov;
    }

    // Tail (n % 4 != 0): block 0.
    if (blockIdx.x == 0) {
        for (int i1 = (n & ~3) + tid; i1 < n; i1 += EVAL_THREADS) {
            out[i1] = interp1(s_tab, x[i1]);
        }
    }
}

extern "C" void kernel_launch(void* const* d_in, const int* in_sizes, int n_in,
                              void* d_out, int out_size) {
    const float* x = (const float*)d_in[0];
    const float* W = (const float*)d_in[1];
    const float* b = (const float*)d_in[2];
    float* out = (float*)d_out;

    const int n = in_sizes[0];

    static int n_sm = 0;
    static bool attr_set = false;
    if (!attr_set) {
        cudaDeviceGetAttribute(&n_sm, cudaDevAttrMultiProcessorCount, 0);
        if (n_sm <= 0) n_sm = 148;
        cudaFuncSetAttribute(eval_kernel,
                             cudaFuncAttributeMaxDynamicSharedMemorySize,
                             SMEM_BYTES);
        attr_set = true;
    }

    build_table_kernel<<<(N_INT + 1 + 255) / 256, 256>>>(W, b);

    cudaLaunchConfig_t cfg = {};
    cfg.gridDim = dim3(2 * n_sm, 1, 1);      // 2 CTAs per SM
    cfg.blockDim = dim3(EVAL_THREADS, 1, 1);
    cfg.dynamicSmemBytes = SMEM_BYTES;
    cfg.stream = 0;
    cudaLaunchAttribute at[1];
    at[0].id = cudaLaunchAttributeProgrammaticStreamSerialization;
    at[0].val.programmaticStreamSerializationAllowed = 1;
    cfg.attrs = at;
    cfg.numAttrs = 1;
    cudaLaunchKernelEx(&cfg, eval_kernel, x, out, n);
}